// round 15
// baseline (speedup 1.0000x reference)
#include <cuda_runtime.h>
#include <cuda_fp16.h>
#include <math.h>
#include <stdint.h>

// ---------------- problem constants ----------------
#define BATCH 4
#define NPIX  65536      // 256*256
#define LHW   64
#define CLAT  32

// fp16 weight store: per batch, 4 layers x 128 rows(n) x 136 halves(k, plain order,
// last 8 = pad). Row stride 272B keeps SMEM loads conflict-free after bulk copy.
__device__ __align__(16) __half g_wh[BATCH * 4 * 128 * 136];
// fp32 small params per batch (1024 floats): bias[4][128] @0, W4[k][2] @512, w4bias[2] @768
__device__ __align__(16) float  g_wf[BATCH * 1024];

// ================= PTX helpers =================
#define MBARRIER_INIT(mb, cnt) \
    asm volatile("mbarrier.init.shared.b64 [%0], %1;" :: "r"((uint32_t)(mb)), "r"((uint32_t)(cnt)) : "memory")
#define MBARRIER_EXPECT_TX(mb, bytes) \
    asm volatile("mbarrier.arrive.expect_tx.shared.b64 _, [%0], %1;" \
                 :: "r"((uint32_t)(mb)), "r"((uint32_t)(bytes)) : "memory")
#define MBARRIER_WAIT_PARITY(mb, par) do { \
    uint32_t _mb = (uint32_t)(mb), _p = (uint32_t)(par), _done; \
    asm volatile("{\n\t.reg .pred p;\n\t" \
        "mbarrier.try_wait.parity.acquire.cta.shared::cta.b64 p, [%1], %2;\n\t" \
        "selp.b32 %0, 1, 0, p;\n\t}" : "=r"(_done) : "r"(_mb), "r"(_p) : "memory"); \
    if (!_done) { \
        asm volatile("{\n\t.reg .pred P1;\n\t" \
            "WL_%=:\n\t" \
            "mbarrier.try_wait.parity.acquire.cta.shared::cta.b64 P1, [%0], %1, 0x989680;\n\t" \
            "@P1 bra.uni WD_%=;\n\t" \
            "bra.uni WL_%=;\n\t" \
            "WD_%=:\n\t}" :: "r"(_mb), "r"(_p) : "memory"); \
    } \
} while (0)
#define BULK_G2S(dst, src, bytes, mb) \
    asm volatile("cp.async.bulk.shared::cluster.global.mbarrier::complete_tx::bytes [%0], [%1], %2, [%3];" \
                 :: "r"((uint32_t)(dst)), "l"(src), "r"((uint32_t)(bytes)), "r"((uint32_t)(mb)) : "memory")
#define LDMATRIX_X4(r0, r1, r2, r3, addr) \
    asm volatile("ldmatrix.sync.aligned.m8n8.x4.shared.b16 {%0,%1,%2,%3}, [%4];" \
                 : "=r"(r0), "=r"(r1), "=r"(r2), "=r"(r3) : "r"(addr))

__device__ __forceinline__ uint32_t smem_to_u32(const void* p) {
    uint32_t a;
    asm("{ .reg .u64 t; cvta.to.shared.u64 t, %1; cvt.u32.u64 %0, t; }" : "=r"(a) : "l"(p));
    return a;
}

// ---------------- kernel A: modulate + normalize + fp16 pack (plain layout) ----------------
__global__ void modulate_kernel(
    const float* __restrict__ w0, const float* __restrict__ w1,
    const float* __restrict__ w2, const float* __restrict__ w3,
    const float* __restrict__ w4,
    const float* __restrict__ m0, const float* __restrict__ m1,
    const float* __restrict__ m2, const float* __restrict__ m3,
    const float* __restrict__ m4)
{
    int gw   = (blockIdx.x * blockDim.x + threadIdx.x) >> 5;
    int lane = threadIdx.x & 31;
    if (gw >= BATCH * 514) return;
    int b = gw / 514;
    int r = gw % 514;
    int layer, o;
    if (r < 512) { layer = r >> 7; o = r & 127; }
    else         { layer = 4;      o = r - 512; }

    if (layer < 4) {
        const float* w; const float* m; int fr;
        switch (layer) {
          case 0:  w = w0; m = m0; fr = 35;  break;
          case 1:  w = w1; m = m1; fr = 128; break;
          case 2:  w = w2; m = m2; fr = 128; break;
          default: w = w3; m = m3; fr = 128; break;
        }
        float ss = 0.f;
        for (int k = lane; k < fr; k += 32) {
            float v = w[k * 128 + o] * m[((size_t)b * fr + k) * 128 + o];
            ss += v * v;
        }
        #pragma unroll
        for (int s = 16; s; s >>= 1) ss += __shfl_xor_sync(0xffffffffu, ss, s);
        float inv = 1.f / fmaxf(sqrtf(ss), 1e-12f);
        __half* dst = g_wh + (size_t)((b * 4 + layer) * 128 + o) * 136;
        for (int k = lane; k < 136; k += 32) {
            float v = (k < fr) ? w[k * 128 + o] * m[((size_t)b * fr + k) * 128 + o] * inv : 0.f;
            dst[k] = __float2half_rn(v);
        }
        if (lane == 0) g_wf[b * 1024 + layer * 128 + o] = w[fr * 128 + o];  // bias
    } else {
        float ss = 0.f;
        for (int k = lane; k < 128; k += 32) {
            float v = w4[k * 2 + o] * m4[((size_t)b * 128 + k) * 2 + o];
            ss += v * v;
        }
        #pragma unroll
        for (int s = 16; s; s >>= 1) ss += __shfl_xor_sync(0xffffffffu, ss, s);
        float inv = 1.f / fmaxf(sqrtf(ss), 1e-12f);
        for (int k = lane; k < 128; k += 32)
            g_wf[b * 1024 + 512 + k * 2 + o] =
                w4[k * 2 + o] * m4[((size_t)b * 128 + k) * 2 + o] * inv;
        if (lane == 0) g_wf[b * 1024 + 768 + o] = w4[128 * 2 + o];
    }
}

// ---------------- kernel B: fp16 m16n8k16 MLP, 64 px / 64 thr (2 warps) / 4 CTAs-per-SM ----
// Warp tile 64(m) x 64(n): warp w owns n-cols w*64..w*64+63, ALL 64 rows (mt=0..3).
// Each warp is sole reader+refiller of its weight half buffer -> no release barriers.
#define ASTR 272          // bytes per A/W row (136 halves); 272/4 mod 32 = 4 -> conflict-free
#define SM_WF0    0
#define SM_WF1    8
#define SMF_BIAS  16      // float idx (byte 64): bias 512 + W4 256 + 2 = 770 floats
#define SMF_W4    528
#define A0_B      4096    // 64 * 272 = 17408  (single A buffer, updated in place)
#define WB0_B     21504   // 64 rows * 272B = 17408 (n half for warp 0)
#define WB1_B     38912
#define SMEM_BYTES 56320

// one layer MMA via ldmatrix.x4: 8 loads -> 32 MMAs per k-step.
template<int KS>
__device__ __forceinline__ void mma_pass(uint32_t a_base, uint32_t w_base,
                                         float acc[4][8][4])
{
    #pragma unroll
    for (int ks = 0; ks < KS; ks++) {
        uint32_t a[4][4];
        #pragma unroll
        for (int mt = 0; mt < 4; mt++)
            LDMATRIX_X4(a[mt][0], a[mt][1], a[mt][2], a[mt][3],
                        a_base + mt * 16 * ASTR + 32 * ks);
        #pragma unroll
        for (int qp = 0; qp < 4; qp++) {
            uint32_t b0, b1, b2, b3;
            LDMATRIX_X4(b0, b1, b2, b3, w_base + qp * 16 * ASTR + 32 * ks);
            #pragma unroll
            for (int mt = 0; mt < 4; mt++) {
                asm volatile(
                    "mma.sync.aligned.m16n8k16.row.col.f32.f16.f16.f32 "
                    "{%0,%1,%2,%3}, {%4,%5,%6,%7}, {%8,%9}, {%0,%1,%2,%3};"
                    : "+f"(acc[mt][2 * qp][0]), "+f"(acc[mt][2 * qp][1]),
                      "+f"(acc[mt][2 * qp][2]), "+f"(acc[mt][2 * qp][3])
                    : "r"(a[mt][0]), "r"(a[mt][1]), "r"(a[mt][2]), "r"(a[mt][3]),
                      "r"(b0), "r"(b1));
                asm volatile(
                    "mma.sync.aligned.m16n8k16.row.col.f32.f16.f16.f32 "
                    "{%0,%1,%2,%3}, {%4,%5,%6,%7}, {%8,%9}, {%0,%1,%2,%3};"
                    : "+f"(acc[mt][2 * qp + 1][0]), "+f"(acc[mt][2 * qp + 1][1]),
                      "+f"(acc[mt][2 * qp + 1][2]), "+f"(acc[mt][2 * qp + 1][3])
                    : "r"(a[mt][0]), "r"(a[mt][1]), "r"(a[mt][2]), "r"(a[mt][3]),
                      "r"(b2), "r"(b3));
            }
        }
    }
}

__global__ __launch_bounds__(64, 4)
void hyponet_kernel(const float* __restrict__ coord,
                    const float* __restrict__ lat,
                    float* __restrict__ out)
{
    extern __shared__ __align__(1024) char smem[];
    float* smf = (float*)smem;
    char*  A0  = smem + A0_B;
    const uint32_t sb = smem_to_u32(smem);

    const int tid  = threadIdx.x;
    const int warp = tid >> 5, lane = tid & 31;
    const int lr = lane >> 2, lc = lane & 3;
    const int h     = warp;                       // n-half owned by this warp
    const int b     = blockIdx.x >> 10;           // 1024 CTAs per batch
    const int pbase = (blockIdx.x & 1023) << 6;   // *64
    const __half* gwh = g_wh + (size_t)b * 4 * 128 * 136;
    const float*  gwf = g_wf + (size_t)b * 1024;

    const uint32_t wf_m = sb + (h ? SM_WF1 : SM_WF0);
    const uint32_t wb_u = sb + (h ? WB1_B : WB0_B);
    const __half* src_h = gwh + h * 8704;         // half h of layer 0 (halves)

    // per-lane ldmatrix base addresses (R12-verified mapping; mt/qp offsets in loop)
    const uint32_t a_base = sb + A0_B + (lane & 15) * ASTR + ((lane >> 4) << 4);
    const uint32_t w_base = wb_u + ((lane & 7) + ((lane >> 4) << 3)) * ASTR
                                 + (((lane >> 3) & 1) << 4);

    if (tid == 0) {
        MBARRIER_INIT(sb + SM_WF0, 1);
        MBARRIER_INIT(sb + SM_WF1, 1);
    }
    __syncthreads();
    if (tid == 0) {
        MBARRIER_EXPECT_TX(sb + SM_WF0, 17408);
        BULK_G2S(sb + WB0_B, gwh + 0 * 8704, 17408, sb + SM_WF0);
        MBARRIER_EXPECT_TX(sb + SM_WF1, 17408);
        BULK_G2S(sb + WB1_B, gwh + 1 * 8704, 17408, sb + SM_WF1);
    }

    // ---- prologue: bias/W4 staging + bilinear latent(32)+coord(3)+pad -> A0 ----
    for (int i = tid; i < 770; i += 64) smf[SMF_BIAS + i] = gwf[i];
    {
        int p = tid, n = pbase + p;
        int y = n >> 8, x = n & 255;
        const float* c = coord + ((size_t)b * NPIX + n) * 3;
        float va[48];
        #pragma unroll
        for (int k = 35; k < 48; k++) va[k] = 0.f;
        va[32] = c[0]; va[33] = c[1]; va[34] = c[2];
        float sy = (y + 0.5f) * 0.25f - 0.5f;
        float sx = (x + 0.5f) * 0.25f - 0.5f;
        float fy0 = floorf(sy), fx0 = floorf(sx);
        float fy = sy - fy0,    fx = sx - fx0;
        int y0 = max(0, min(LHW - 1, (int)fy0));
        int y1 = max(0, min(LHW - 1, (int)fy0 + 1));
        int x0 = max(0, min(LHW - 1, (int)fx0));
        int x1 = max(0, min(LHW - 1, (int)fx0 + 1));
        float w00 = (1.f - fy) * (1.f - fx), w01 = (1.f - fy) * fx;
        float w10 = fy * (1.f - fx),         w11 = fy * fx;
        const float* base = lat + (size_t)b * LHW * LHW * CLAT;
        const float4* q00 = (const float4*)(base + (y0 * LHW + x0) * CLAT);
        const float4* q01 = (const float4*)(base + (y0 * LHW + x1) * CLAT);
        const float4* q10 = (const float4*)(base + (y1 * LHW + x0) * CLAT);
        const float4* q11 = (const float4*)(base + (y1 * LHW + x1) * CLAT);
        #pragma unroll
        for (int k = 0; k < 8; k++) {
            float4 a = q00[k], bb = q01[k], cc = q10[k], dd = q11[k];
            va[4 * k + 0] = w00 * a.x + w01 * bb.x + w10 * cc.x + w11 * dd.x;
            va[4 * k + 1] = w00 * a.y + w01 * bb.y + w10 * cc.y + w11 * dd.y;
            va[4 * k + 2] = w00 * a.z + w01 * bb.z + w10 * cc.z + w11 * dd.z;
            va[4 * k + 3] = w00 * a.w + w01 * bb.w + w10 * cc.w + w11 * dd.w;
        }
        __half2* arow = (__half2*)(A0 + p * ASTR);
        #pragma unroll
        for (int j = 0; j < 24; j++)
            arow[j] = __floats2half2_rn(va[2 * j], va[2 * j + 1]);
    }
    __syncthreads();

    // ---- 4 layers: wait weights -> MMA -> refill own buffer -> bar -> sin in place -> bar ----
    #define LAYER_PASS(L, KS) do { \
        const float* biasL = smf + SMF_BIAS + (L) * 128; \
        float acc[4][8][4]; \
        _Pragma("unroll") \
        for (int q = 0; q < 8; q++) { \
            float2 bv = *(const float2*)(biasL + h * 64 + q * 8 + 2 * lc); \
            _Pragma("unroll") \
            for (int mt = 0; mt < 4; mt++) { \
                acc[mt][q][0] = bv.x; acc[mt][q][1] = bv.y; \
                acc[mt][q][2] = bv.x; acc[mt][q][3] = bv.y; \
            } \
        } \
        MBARRIER_WAIT_PARITY(wf_m, (L) & 1); \
        mma_pass<KS>(a_base, w_base, acc); \
        if (lane == 0 && (L) < 3) { \
            MBARRIER_EXPECT_TX(wf_m, 17408); \
            BULK_G2S(wb_u, src_h + ((L) + 1) * 17408, 17408, wf_m); \
        } \
        __syncthreads(); \
        _Pragma("unroll") \
        for (int mt = 0; mt < 4; mt++) { \
            _Pragma("unroll") \
            for (int q = 0; q < 8; q++) { \
                int n0 = h * 64 + q * 8 + 2 * lc; \
                int r0 = mt * 16 + lr; \
                __half2 v01 = __floats2half2_rn(__sinf(acc[mt][q][0]), __sinf(acc[mt][q][1])); \
                __half2 v23 = __floats2half2_rn(__sinf(acc[mt][q][2]), __sinf(acc[mt][q][3])); \
                *(__half2*)(A0 + r0 * ASTR + 2 * n0)       = v01; \
                *(__half2*)(A0 + (r0 + 8) * ASTR + 2 * n0) = v23; \
            } \
        } \
        __syncthreads(); \
    } while (0)

    LAYER_PASS(0, 3);
    LAYER_PASS(1, 8);
    LAYER_PASS(2, 8);
    LAYER_PASS(3, 8);
    #undef LAYER_PASS

    // ---- final: 128 -> 2 dot + 0.5 (fp32); each thread does one pixel, both outputs ----
    {
        int p = tid;
        float acc0 = smf[SMF_W4 + 256];
        float acc1 = smf[SMF_W4 + 257];
        const uint4* arow = (const uint4*)(A0 + p * ASTR);
        const float* w4 = smf + SMF_W4;
        #pragma unroll
        for (int jb = 0; jb < 16; jb++) {
            uint4 v = arow[jb];
            const __half2* h2 = (const __half2*)&v;
            #pragma unroll
            for (int t = 0; t < 4; t++) {
                float2 av = __half22float2(h2[t]);
                acc0 += av.x * w4[16 * jb + 4 * t];
                acc1 += av.x * w4[16 * jb + 4 * t + 1];
                acc0 += av.y * w4[16 * jb + 4 * t + 2];
                acc1 += av.y * w4[16 * jb + 4 * t + 3];
            }
        }
        ((float2*)out)[(size_t)b * NPIX + pbase + p] = make_float2(acc0 + 0.5f, acc1 + 0.5f);
    }
}

// ---------------- launch ----------------
extern "C" void kernel_launch(void* const* d_in, const int* in_sizes, int n_in,
                              void* d_out, int out_size)
{
    const float* coord = (const float*)d_in[0];
    const float* lat   = (const float*)d_in[1];

    modulate_kernel<<<(2056 * 32 + 255) / 256, 256>>>(
        (const float*)d_in[2], (const float*)d_in[3], (const float*)d_in[4],
        (const float*)d_in[5], (const float*)d_in[6],
        (const float*)d_in[7], (const float*)d_in[8], (const float*)d_in[9],
        (const float*)d_in[10], (const float*)d_in[11]);

    cudaFuncSetAttribute(hyponet_kernel,
                         cudaFuncAttributeMaxDynamicSharedMemorySize, SMEM_BYTES);
    hyponet_kernel<<<BATCH * (NPIX / 64), 64, SMEM_BYTES>>>(coord, lat, (float*)d_out);
}

// round 16
// speedup vs baseline: 1.0181x; 1.0181x over previous
#include <cuda_runtime.h>
#include <cuda_fp16.h>
#include <math.h>
#include <stdint.h>

// ---------------- problem constants ----------------
#define BATCH 4
#define NPIX  65536      // 256*256
#define LHW   64
#define CLAT  32

// fp16 weight store: per batch, 4 layers x 128 rows(n) x 136 halves(k, plain order,
// last 8 = pad). Row stride 272B keeps SMEM loads conflict-free after bulk copy.
__device__ __align__(16) __half g_wh[BATCH * 4 * 128 * 136];
// fp32 small params per batch (1024 floats): bias[4][128] @0, W4[k][2] @512, w4bias[2] @768
__device__ __align__(16) float  g_wf[BATCH * 1024];

// ================= PTX helpers =================
#define MBARRIER_INIT(mb, cnt) \
    asm volatile("mbarrier.init.shared.b64 [%0], %1;" :: "r"((uint32_t)(mb)), "r"((uint32_t)(cnt)) : "memory")
#define MBARRIER_ARRIVE(mb) \
    asm volatile("mbarrier.arrive.shared.b64 _, [%0];" :: "r"((uint32_t)(mb)) : "memory")
#define MBARRIER_EXPECT_TX(mb, bytes) \
    asm volatile("mbarrier.arrive.expect_tx.shared.b64 _, [%0], %1;" \
                 :: "r"((uint32_t)(mb)), "r"((uint32_t)(bytes)) : "memory")
#define MBARRIER_WAIT_PARITY(mb, par) do { \
    uint32_t _mb = (uint32_t)(mb), _p = (uint32_t)(par), _done; \
    asm volatile("{\n\t.reg .pred p;\n\t" \
        "mbarrier.try_wait.parity.acquire.cta.shared::cta.b64 p, [%1], %2;\n\t" \
        "selp.b32 %0, 1, 0, p;\n\t}" : "=r"(_done) : "r"(_mb), "r"(_p) : "memory"); \
    if (!_done) { \
        asm volatile("{\n\t.reg .pred P1;\n\t" \
            "WL_%=:\n\t" \
            "mbarrier.try_wait.parity.acquire.cta.shared::cta.b64 P1, [%0], %1, 0x989680;\n\t" \
            "@P1 bra.uni WD_%=;\n\t" \
            "bra.uni WL_%=;\n\t" \
            "WD_%=:\n\t}" :: "r"(_mb), "r"(_p) : "memory"); \
    } \
} while (0)
#define BULK_G2S(dst, src, bytes, mb) \
    asm volatile("cp.async.bulk.shared::cluster.global.mbarrier::complete_tx::bytes [%0], [%1], %2, [%3];" \
                 :: "r"((uint32_t)(dst)), "l"(src), "r"((uint32_t)(bytes)), "r"((uint32_t)(mb)) : "memory")
#define LDMATRIX_X4(r0, r1, r2, r3, addr) \
    asm volatile("ldmatrix.sync.aligned.m8n8.x4.shared.b16 {%0,%1,%2,%3}, [%4];" \
                 : "=r"(r0), "=r"(r1), "=r"(r2), "=r"(r3) : "r"(addr))

__device__ __forceinline__ uint32_t smem_to_u32(const void* p) {
    uint32_t a;
    asm("{ .reg .u64 t; cvta.to.shared.u64 t, %1; cvt.u32.u64 %0, t; }" : "=r"(a) : "l"(p));
    return a;
}

// ---------------- kernel A: modulate + normalize + fp16 pack (plain layout) ----------------
__global__ void modulate_kernel(
    const float* __restrict__ w0, const float* __restrict__ w1,
    const float* __restrict__ w2, const float* __restrict__ w3,
    const float* __restrict__ w4,
    const float* __restrict__ m0, const float* __restrict__ m1,
    const float* __restrict__ m2, const float* __restrict__ m3,
    const float* __restrict__ m4)
{
    int gw   = (blockIdx.x * blockDim.x + threadIdx.x) >> 5;
    int lane = threadIdx.x & 31;
    if (gw >= BATCH * 514) return;
    int b = gw / 514;
    int r = gw % 514;
    int layer, o;
    if (r < 512) { layer = r >> 7; o = r & 127; }
    else         { layer = 4;      o = r - 512; }

    if (layer < 4) {
        const float* w; const float* m; int fr;
        switch (layer) {
          case 0:  w = w0; m = m0; fr = 35;  break;
          case 1:  w = w1; m = m1; fr = 128; break;
          case 2:  w = w2; m = m2; fr = 128; break;
          default: w = w3; m = m3; fr = 128; break;
        }
        float ss = 0.f;
        for (int k = lane; k < fr; k += 32) {
            float v = w[k * 128 + o] * m[((size_t)b * fr + k) * 128 + o];
            ss += v * v;
        }
        #pragma unroll
        for (int s = 16; s; s >>= 1) ss += __shfl_xor_sync(0xffffffffu, ss, s);
        float inv = 1.f / fmaxf(sqrtf(ss), 1e-12f);
        __half* dst = g_wh + (size_t)((b * 4 + layer) * 128 + o) * 136;
        for (int k = lane; k < 136; k += 32) {
            float v = (k < fr) ? w[k * 128 + o] * m[((size_t)b * fr + k) * 128 + o] * inv : 0.f;
            dst[k] = __float2half_rn(v);
        }
        if (lane == 0) g_wf[b * 1024 + layer * 128 + o] = w[fr * 128 + o];  // bias
    } else {
        float ss = 0.f;
        for (int k = lane; k < 128; k += 32) {
            float v = w4[k * 2 + o] * m4[((size_t)b * 128 + k) * 2 + o];
            ss += v * v;
        }
        #pragma unroll
        for (int s = 16; s; s >>= 1) ss += __shfl_xor_sync(0xffffffffu, ss, s);
        float inv = 1.f / fmaxf(sqrtf(ss), 1e-12f);
        for (int k = lane; k < 128; k += 32)
            g_wf[b * 1024 + 512 + k * 2 + o] =
                w4[k * 2 + o] * m4[((size_t)b * 128 + k) * 2 + o] * inv;
        if (lane == 0) g_wf[b * 1024 + 768 + o] = w4[128 * 2 + o];
    }
}

// ---------------- kernel B: fp16 m16n8k16 MLP, 64 px / 128 thr / 3 CTAs-per-SM ----------------
// R12-proven layout + software-pipelined fragment loads (regs headroom from occ=3).
#define ASTR 272          // bytes per A/W row (136 halves); 272/4 mod 32 = 4 -> conflict-free
#define SM_WF0    0
#define SM_WF1    8
#define SM_WREL0  16
#define SM_WREL1  24
#define SMF_BIAS  16      // float idx (byte 64): bias 512 + W4 256 + 2 = 770 floats
#define SMF_W4    528
#define A0_B      4096    // 64 * 272 = 17408  (single A buffer, updated in place)
#define WB0_B     21504   // 64 rows * 272B = 17408 (n half for warp pair 0)
#define WB1_B     38912
#define SMEM_BYTES 56320

// one layer MMA via ldmatrix.x4, double-buffered fragments: load k+1 before MMA k.
template<int KS>
__device__ __forceinline__ void mma_pass(uint32_t a_base, uint32_t w_base,
                                         float acc[2][8][4])
{
    uint32_t a[2][2][4];   // [buf][mt][reg]
    uint32_t bf[2][4][4];  // [buf][qp][reg]
    #pragma unroll
    for (int mt = 0; mt < 2; mt++)
        LDMATRIX_X4(a[0][mt][0], a[0][mt][1], a[0][mt][2], a[0][mt][3],
                    a_base + mt * 16 * ASTR);
    #pragma unroll
    for (int qp = 0; qp < 4; qp++)
        LDMATRIX_X4(bf[0][qp][0], bf[0][qp][1], bf[0][qp][2], bf[0][qp][3],
                    w_base + qp * 16 * ASTR);
    #pragma unroll
    for (int ks = 0; ks < KS; ks++) {
        const int cur = ks & 1, nxt = cur ^ 1;
        if (ks + 1 < KS) {
            #pragma unroll
            for (int mt = 0; mt < 2; mt++)
                LDMATRIX_X4(a[nxt][mt][0], a[nxt][mt][1], a[nxt][mt][2], a[nxt][mt][3],
                            a_base + mt * 16 * ASTR + 32 * (ks + 1));
            #pragma unroll
            for (int qp = 0; qp < 4; qp++)
                LDMATRIX_X4(bf[nxt][qp][0], bf[nxt][qp][1], bf[nxt][qp][2], bf[nxt][qp][3],
                            w_base + qp * 16 * ASTR + 32 * (ks + 1));
        }
        #pragma unroll
        for (int qp = 0; qp < 4; qp++) {
            #pragma unroll
            for (int mt = 0; mt < 2; mt++) {
                asm volatile(
                    "mma.sync.aligned.m16n8k16.row.col.f32.f16.f16.f32 "
                    "{%0,%1,%2,%3}, {%4,%5,%6,%7}, {%8,%9}, {%0,%1,%2,%3};"
                    : "+f"(acc[mt][2 * qp][0]), "+f"(acc[mt][2 * qp][1]),
                      "+f"(acc[mt][2 * qp][2]), "+f"(acc[mt][2 * qp][3])
                    : "r"(a[cur][mt][0]), "r"(a[cur][mt][1]),
                      "r"(a[cur][mt][2]), "r"(a[cur][mt][3]),
                      "r"(bf[cur][qp][0]), "r"(bf[cur][qp][1]));
                asm volatile(
                    "mma.sync.aligned.m16n8k16.row.col.f32.f16.f16.f32 "
                    "{%0,%1,%2,%3}, {%4,%5,%6,%7}, {%8,%9}, {%0,%1,%2,%3};"
                    : "+f"(acc[mt][2 * qp + 1][0]), "+f"(acc[mt][2 * qp + 1][1]),
                      "+f"(acc[mt][2 * qp + 1][2]), "+f"(acc[mt][2 * qp + 1][3])
                    : "r"(a[cur][mt][0]), "r"(a[cur][mt][1]),
                      "r"(a[cur][mt][2]), "r"(a[cur][mt][3]),
                      "r"(bf[cur][qp][2]), "r"(bf[cur][qp][3]));
            }
        }
    }
}

__global__ __launch_bounds__(128, 3)
void hyponet_kernel(const float* __restrict__ coord,
                    const float* __restrict__ lat,
                    float* __restrict__ out)
{
    extern __shared__ __align__(1024) char smem[];
    float* smf = (float*)smem;
    char*  A0  = smem + A0_B;
    const uint32_t sb = smem_to_u32(smem);

    const int tid  = threadIdx.x;
    const int warp = tid >> 5, lane = tid & 31;
    const int lr = lane >> 2, lc = lane & 3;
    const int mbase = (warp & 1) * 32;
    const int h     = warp >> 1;                  // n-half owned by this warp pair
    const int b     = blockIdx.x >> 10;           // 1024 CTAs per batch
    const int pbase = (blockIdx.x & 1023) << 6;   // *64
    const __half* gwh = g_wh + (size_t)b * 4 * 128 * 136;
    const float*  gwf = g_wf + (size_t)b * 1024;

    const uint32_t wf_m   = sb + (h ? SM_WF1 : SM_WF0);
    const uint32_t wrel_m = sb + (h ? SM_WREL1 : SM_WREL0);
    const uint32_t wb_u   = sb + (h ? WB1_B : WB0_B);
    const __half* src_h = gwh + h * 8704;         // half h of layer 0 (halves)

    // per-lane ldmatrix base addresses (R12-verified mapping)
    const uint32_t a_base = sb + A0_B + (mbase + (lane & 15)) * ASTR + ((lane >> 4) << 4);
    const uint32_t w_base = wb_u + ((lane & 7) + ((lane >> 4) << 3)) * ASTR
                                 + (((lane >> 3) & 1) << 4);

    if (tid == 0) {
        MBARRIER_INIT(sb + SM_WF0, 1);
        MBARRIER_INIT(sb + SM_WF1, 1);
        MBARRIER_INIT(sb + SM_WREL0, 2);
        MBARRIER_INIT(sb + SM_WREL1, 2);
    }
    __syncthreads();
    if (tid == 0) {
        MBARRIER_EXPECT_TX(sb + SM_WF0, 17408);
        BULK_G2S(sb + WB0_B, gwh + 0 * 8704, 17408, sb + SM_WF0);
        MBARRIER_EXPECT_TX(sb + SM_WF1, 17408);
        BULK_G2S(sb + WB1_B, gwh + 1 * 8704, 17408, sb + SM_WF1);
    }

    // ---- prologue: bilinear latent(32) + coord(3) + pad -> A0 rows (plain halves) ----
    if (tid < 64) {
        int p = tid, n = pbase + p;
        int y = n >> 8, x = n & 255;
        const float* c = coord + ((size_t)b * NPIX + n) * 3;
        float va[48];
        #pragma unroll
        for (int k = 35; k < 48; k++) va[k] = 0.f;
        va[32] = c[0]; va[33] = c[1]; va[34] = c[2];
        float sy = (y + 0.5f) * 0.25f - 0.5f;
        float sx = (x + 0.5f) * 0.25f - 0.5f;
        float fy0 = floorf(sy), fx0 = floorf(sx);
        float fy = sy - fy0,    fx = sx - fx0;
        int y0 = max(0, min(LHW - 1, (int)fy0));
        int y1 = max(0, min(LHW - 1, (int)fy0 + 1));
        int x0 = max(0, min(LHW - 1, (int)fx0));
        int x1 = max(0, min(LHW - 1, (int)fx0 + 1));
        float w00 = (1.f - fy) * (1.f - fx), w01 = (1.f - fy) * fx;
        float w10 = fy * (1.f - fx),         w11 = fy * fx;
        const float* base = lat + (size_t)b * LHW * LHW * CLAT;
        const float4* q00 = (const float4*)(base + (y0 * LHW + x0) * CLAT);
        const float4* q01 = (const float4*)(base + (y0 * LHW + x1) * CLAT);
        const float4* q10 = (const float4*)(base + (y1 * LHW + x0) * CLAT);
        const float4* q11 = (const float4*)(base + (y1 * LHW + x1) * CLAT);
        #pragma unroll
        for (int k = 0; k < 8; k++) {
            float4 a = q00[k], bb = q01[k], cc = q10[k], dd = q11[k];
            va[4 * k + 0] = w00 * a.x + w01 * bb.x + w10 * cc.x + w11 * dd.x;
            va[4 * k + 1] = w00 * a.y + w01 * bb.y + w10 * cc.y + w11 * dd.y;
            va[4 * k + 2] = w00 * a.z + w01 * bb.z + w10 * cc.z + w11 * dd.z;
            va[4 * k + 3] = w00 * a.w + w01 * bb.w + w10 * cc.w + w11 * dd.w;
        }
        __half2* arow = (__half2*)(A0 + p * ASTR);
        #pragma unroll
        for (int j = 0; j < 24; j++)
            arow[j] = __floats2half2_rn(va[2 * j], va[2 * j + 1]);
    } else {
        for (int i = tid - 64; i < 770; i += 64) smf[SMF_BIAS + i] = gwf[i];
    }
    __syncthreads();

    // ---- 4 layers: wait weights -> MMA(pipelined) -> release/refill -> bar -> sin -> bar ----
    #define LAYER_PASS(L, KS) do { \
        const float* biasL = smf + SMF_BIAS + (L) * 128; \
        float acc[2][8][4]; \
        _Pragma("unroll") \
        for (int q = 0; q < 8; q++) { \
            float2 bv = *(const float2*)(biasL + h * 64 + q * 8 + 2 * lc); \
            acc[0][q][0] = bv.x; acc[0][q][1] = bv.y; \
            acc[0][q][2] = bv.x; acc[0][q][3] = bv.y; \
            acc[1][q][0] = bv.x; acc[1][q][1] = bv.y; \
            acc[1][q][2] = bv.x; acc[1][q][3] = bv.y; \
        } \
        MBARRIER_WAIT_PARITY(wf_m, (L) & 1); \
        mma_pass<KS>(a_base, w_base, acc); \
        if (lane == 0) MBARRIER_ARRIVE(wrel_m); \
        if ((warp & 1) == 0 && (L) < 3) { \
            MBARRIER_WAIT_PARITY(wrel_m, (L) & 1); \
            if (lane == 0) { \
                MBARRIER_EXPECT_TX(wf_m, 17408); \
                BULK_G2S(wb_u, src_h + ((L) + 1) * 17408, 17408, wf_m); \
            } \
        } \
        __syncthreads(); \
        _Pragma("unroll") \
        for (int mt = 0; mt < 2; mt++) { \
            _Pragma("unroll") \
            for (int q = 0; q < 8; q++) { \
                int n0 = h * 64 + q * 8 + 2 * lc; \
                int r0 = mbase + mt * 16 + lr; \
                __half2 v01 = __floats2half2_rn(__sinf(acc[mt][q][0]), __sinf(acc[mt][q][1])); \
                __half2 v23 = __floats2half2_rn(__sinf(acc[mt][q][2]), __sinf(acc[mt][q][3])); \
                *(__half2*)(A0 + r0 * ASTR + 2 * n0)       = v01; \
                *(__half2*)(A0 + (r0 + 8) * ASTR + 2 * n0) = v23; \
            } \
        } \
        __syncthreads(); \
    } while (0)

    LAYER_PASS(0, 3);
    LAYER_PASS(1, 8);
    LAYER_PASS(2, 8);
    LAYER_PASS(3, 8);
    #undef LAYER_PASS

    // ---- final: 128 -> 2 dot + 0.5 (fp32); activations in A0, LDS.128 row reads ----
    {
        int o = tid & 1, p = tid >> 1;
        float acc = smf[SMF_W4 + 256 + o];
        const uint4* arow = (const uint4*)(A0 + p * ASTR);
        const float* w4 = smf + SMF_W4 + o;
        #pragma unroll
        for (int jb = 0; jb < 16; jb++) {
            uint4 v = arow[jb];
            const __half2* h2 = (const __half2*)&v;
            #pragma unroll
            for (int t = 0; t < 4; t++) {
                float2 av = __half22float2(h2[t]);
                acc += av.x * w4[16 * jb + 4 * t];
                acc += av.y * w4[16 * jb + 4 * t + 2];
            }
        }
        out[((size_t)b * NPIX + pbase + p) * 2 + o] = acc + 0.5f;
    }
}

// ---------------- launch ----------------
extern "C" void kernel_launch(void* const* d_in, const int* in_sizes, int n_in,
                              void* d_out, int out_size)
{
    const float* coord = (const float*)d_in[0];
    const float* lat   = (const float*)d_in[1];

    modulate_kernel<<<(2056 * 32 + 255) / 256, 256>>>(
        (const float*)d_in[2], (const float*)d_in[3], (const float*)d_in[4],
        (const float*)d_in[5], (const float*)d_in[6],
        (const float*)d_in[7], (const float*)d_in[8], (const float*)d_in[9],
        (const float*)d_in[10], (const float*)d_in[11]);

    cudaFuncSetAttribute(hyponet_kernel,
                         cudaFuncAttributeMaxDynamicSharedMemorySize, SMEM_BYTES);
    hyponet_kernel<<<BATCH * (NPIX / 64), 128, SMEM_BYTES>>>(coord, lat, (float*)d_out);
}